// round 1
// baseline (speedup 1.0000x reference)
#include <cuda_runtime.h>
#include <math.h>

// ---------------------------------------------------------------------------
// Problem constants
// ---------------------------------------------------------------------------
#define NA   256      // num agents
#define HID  128
#define ACT  5
#define NH   4
#define DD   144      // concat dim
#define EE   576      // embed dim
#define HDH  144      // per-head dim
#define OBS_RX 4
#define OBS_RY 2

// ---------------------------------------------------------------------------
// Device scratch (no allocations allowed)
// ---------------------------------------------------------------------------
__device__ float    g_C[NA * DD];            // concat features
__device__ unsigned g_mask[NA * 8];          // bitmask rows
__device__ float    g_P[3][NA * EE];         // outer projections
__device__ float    g_QKV[3][NA * EE];       // inner projections (q2,k2,v2 flat)
__device__ float    g_S[NH * NA * NA];       // shared scores per head
__device__ float    g_G[NA * EE];            // masked-context sums
__device__ float    g_cnt[NA];               // |J_i|
__device__ float    g_T[NA * EE];            // G@Wo_proj + cnt*bo
__device__ float    g_h[NA * DD];            // final per-agent feature

// ---------------------------------------------------------------------------
// Setup: mask bits + C = [obs_encoder(hidden), action]
// ---------------------------------------------------------------------------
__global__ void setup_kernel(const float* __restrict__ hid,
                             const float* __restrict__ act,
                             const int*   __restrict__ state,
                             const float* __restrict__ W_enc,
                             const float* __restrict__ b_enc)
{
    __shared__ int px[NA], py[NA];
    int i = threadIdx.x;
    px[i] = state[2 * i];
    py[i] = state[2 * i + 1];
    __syncthreads();

    unsigned w[8] = {0, 0, 0, 0, 0, 0, 0, 0};
    int xi = px[i], yi = py[i];
    for (int j = i + 1; j < NA; ++j) {
        int dx = abs(xi - px[j]);
        int dy = abs(yi - py[j]);
        if (dx <= OBS_RX && dy <= OBS_RY) w[j >> 5] |= (1u << (j & 31));
    }
#pragma unroll
    for (int t = 0; t < 8; ++t) g_mask[i * 8 + t] = w[t];

    // obs = hid[i] @ W_enc + b_enc  (W_enc is [128,16] row-major)
    float o[16];
#pragma unroll
    for (int t = 0; t < 16; ++t) o[t] = b_enc[t];
    for (int d = 0; d < HID; ++d) {
        float hv = hid[i * HID + d];
#pragma unroll
        for (int t = 0; t < 16; ++t) o[t] += hv * W_enc[d * 16 + t];
    }
#pragma unroll
    for (int t = 0; t < 16; ++t) g_C[i * DD + t] = o[t];
    for (int d = 0; d < HID; ++d) g_C[i * DD + 16 + d] = act[i * HID + d];
}

// ---------------------------------------------------------------------------
// Generic fp32 GEMM: C = A[MxK] @ B[KxN] (+ rowScale[m]*bias[n])
// 64x64 block tile, 16 K-tile, 256 threads, 4x4 per thread.
// Requires: M % 64 == 0, K % 16 == 0, lda/ldb multiples of 4, 16B-aligned ptrs.
// N may be arbitrary (guarded).
// ---------------------------------------------------------------------------
__global__ __launch_bounds__(256)
void gemm_k(const float* __restrict__ A, int lda,
            const float* __restrict__ B, int ldb,
            const float* __restrict__ bias,
            const float* __restrict__ rowScale,
            float* __restrict__ C, int ldc,
            int M, int N, int K)
{
    __shared__ float As[16][64];
    __shared__ float Bs[16][64];

    const int tid = threadIdx.x;
    const int tx  = tid & 15;    // n dir
    const int ty  = tid >> 4;    // m dir
    const int m0  = blockIdx.y * 64;
    const int n0  = blockIdx.x * 64;

    float acc[4][4];
#pragma unroll
    for (int i = 0; i < 4; ++i)
#pragma unroll
        for (int j = 0; j < 4; ++j) acc[i][j] = 0.f;

    for (int k0 = 0; k0 < K; k0 += 16) {
        // A tile 64x16: thread loads float4 along k
        {
            int m = tid >> 2;
            int k = (tid & 3) * 4;
            float4 v = *reinterpret_cast<const float4*>(&A[(m0 + m) * lda + k0 + k]);
            As[k + 0][m] = v.x; As[k + 1][m] = v.y;
            As[k + 2][m] = v.z; As[k + 3][m] = v.w;
        }
        // B tile 16x64: thread loads float4 along n
        {
            int k = tid >> 4;
            int n = (tid & 15) * 4;
            float4 v;
            if (n0 + n + 3 < N) {
                v = *reinterpret_cast<const float4*>(&B[(k0 + k) * ldb + n0 + n]);
            } else {
                v.x = (n0 + n + 0 < N) ? B[(k0 + k) * ldb + n0 + n + 0] : 0.f;
                v.y = (n0 + n + 1 < N) ? B[(k0 + k) * ldb + n0 + n + 1] : 0.f;
                v.z = (n0 + n + 2 < N) ? B[(k0 + k) * ldb + n0 + n + 2] : 0.f;
                v.w = (n0 + n + 3 < N) ? B[(k0 + k) * ldb + n0 + n + 3] : 0.f;
            }
            Bs[k][n + 0] = v.x; Bs[k][n + 1] = v.y;
            Bs[k][n + 2] = v.z; Bs[k][n + 3] = v.w;
        }
        __syncthreads();
#pragma unroll
        for (int kk = 0; kk < 16; ++kk) {
            float a[4], b[4];
#pragma unroll
            for (int i = 0; i < 4; ++i) a[i] = As[kk][ty * 4 + i];
#pragma unroll
            for (int j = 0; j < 4; ++j) b[j] = Bs[kk][tx * 4 + j];
#pragma unroll
            for (int i = 0; i < 4; ++i)
#pragma unroll
                for (int j = 0; j < 4; ++j) acc[i][j] += a[i] * b[j];
        }
        __syncthreads();
    }

#pragma unroll
    for (int i = 0; i < 4; ++i) {
        int m = m0 + ty * 4 + i;
        if (m >= M) continue;
        float rs = rowScale ? rowScale[m] : 1.f;
#pragma unroll
        for (int j = 0; j < 4; ++j) {
            int n = n0 + tx * 4 + j;
            if (n >= N) continue;
            float v = acc[i][j];
            if (bias) v += rs * bias[n];
            C[m * ldc + n] = v;
        }
    }
}

// ---------------------------------------------------------------------------
// S[h] = scale * q2_h @ k2_h^T : per-head NT GEMM, blockIdx.z = head
// A = q + h*144 (lda=576), B = k + h*144 (ldb=576), C = S + h*NA*NA
// M=N=256, K=144.
// ---------------------------------------------------------------------------
__global__ __launch_bounds__(256)
void gemm_nt_heads(const float* __restrict__ Q, const float* __restrict__ Kk,
                   float* __restrict__ S, float scale)
{
    __shared__ float As[16][64];
    __shared__ float Bs[16][64];

    const int h   = blockIdx.z;
    const float* A = Q  + h * HDH;   // within-row offset, lda = EE
    const float* B = Kk + h * HDH;
    float* C = S + h * NA * NA;

    const int tid = threadIdx.x;
    const int tx  = tid & 15;
    const int ty  = tid >> 4;
    const int m0  = blockIdx.y * 64;
    const int n0  = blockIdx.x * 64;

    float acc[4][4];
#pragma unroll
    for (int i = 0; i < 4; ++i)
#pragma unroll
        for (int j = 0; j < 4; ++j) acc[i][j] = 0.f;

    for (int k0 = 0; k0 < HDH; k0 += 16) {
        {
            int m = tid >> 2;
            int k = (tid & 3) * 4;
            float4 v = *reinterpret_cast<const float4*>(&A[(m0 + m) * EE + k0 + k]);
            As[k + 0][m] = v.x; As[k + 1][m] = v.y;
            As[k + 2][m] = v.z; As[k + 3][m] = v.w;
        }
        {
            int m = tid >> 2;
            int k = (tid & 3) * 4;
            float4 v = *reinterpret_cast<const float4*>(&B[(n0 + m) * EE + k0 + k]);
            Bs[k + 0][m] = v.x; Bs[k + 1][m] = v.y;
            Bs[k + 2][m] = v.z; Bs[k + 3][m] = v.w;
        }
        __syncthreads();
#pragma unroll
        for (int kk = 0; kk < 16; ++kk) {
            float a[4], b[4];
#pragma unroll
            for (int i = 0; i < 4; ++i) a[i] = As[kk][ty * 4 + i];
#pragma unroll
            for (int j = 0; j < 4; ++j) b[j] = Bs[kk][tx * 4 + j];
#pragma unroll
            for (int i = 0; i < 4; ++i)
#pragma unroll
                for (int j = 0; j < 4; ++j) acc[i][j] += a[i] * b[j];
        }
        __syncthreads();
    }

#pragma unroll
    for (int i = 0; i < 4; ++i) {
        int m = m0 + ty * 4 + i;
#pragma unroll
        for (int j = 0; j < 4; ++j) {
            int n = n0 + tx * 4 + j;
            C[m * NA + n] = scale * acc[i][j];
        }
    }
}

// ---------------------------------------------------------------------------
// Per-agent attention: J_i from mask row, softmax rows of S restricted to J_i,
// sum rows -> weights w[h,k]; G[i] = w @ v2 (sparse over J_i); cnt[i] = |J_i|.
// One block per agent.
// ---------------------------------------------------------------------------
__global__ void attn_kernel(const float* __restrict__ v2)
{
    const int i   = blockIdx.x;
    const int tid = threadIdx.x;

    __shared__ int   Jl[NA];
    __shared__ int   sn;
    __shared__ float w[NH * NA];

    if (tid == 0) {
        int n = 0;
        for (int t = 0; t < 8; ++t) {
            unsigned bits = g_mask[i * 8 + t];
            while (bits) {
                int b = __ffs(bits) - 1;
                Jl[n++] = t * 32 + b;
                bits &= bits - 1;
            }
        }
        sn = n;
        g_cnt[i] = (float)n;
    }
    for (int t = tid; t < NH * NA; t += blockDim.x) w[t] = 0.f;
    __syncthreads();

    const int n = sn;
    if (n == 0) {
        for (int e = tid; e < EE; e += blockDim.x) g_G[i * EE + e] = 0.f;
        return;
    }

    // each thread: one (head, j) pair; accumulate softmax row into w[h, :]
    for (int p = tid; p < NH * n; p += blockDim.x) {
        int h  = p & 3;
        int jj = Jl[p >> 2];
        const float* row = g_S + h * NA * NA + jj * NA;
        float m = -1e30f;
        for (int t = 0; t < n; ++t) m = fmaxf(m, row[Jl[t]]);
        float sum = 0.f;
        for (int t = 0; t < n; ++t) sum += expf(row[Jl[t]] - m);
        float inv = 1.f / sum;
        for (int t = 0; t < n; ++t)
            atomicAdd(&w[h * NA + t], expf(row[Jl[t]] - m) * inv);
    }
    __syncthreads();

    // G[i, e] = sum_t w[h(e), t] * v2[Jl[t], e]
    for (int e = tid; e < EE; e += blockDim.x) {
        int h = e / HDH;
        float acc = 0.f;
        for (int t = 0; t < n; ++t)
            acc += w[h * NA + t] * v2[Jl[t] * EE + e];
        g_G[i * EE + e] = acc;
    }
}

// ---------------------------------------------------------------------------
// Dueling head: Q = V + A - mean(A)
// ---------------------------------------------------------------------------
__global__ void final_kernel(const float* __restrict__ W_val, const float* __restrict__ b_val,
                             const float* __restrict__ W_adv, const float* __restrict__ b_adv,
                             float* __restrict__ out)
{
    int i = threadIdx.x;  // 256 threads
    const float* hr = g_h + i * DD;
    float V = b_val[0];
    float A[ACT];
#pragma unroll
    for (int a = 0; a < ACT; ++a) A[a] = b_adv[a];
    for (int d = 0; d < DD; ++d) {
        float hv = hr[d];
        V += hv * W_val[d];
#pragma unroll
        for (int a = 0; a < ACT; ++a) A[a] += hv * W_adv[d * ACT + a];
    }
    float mean = 0.f;
#pragma unroll
    for (int a = 0; a < ACT; ++a) mean += A[a];
    mean *= (1.f / ACT);
#pragma unroll
    for (int a = 0; a < ACT; ++a) out[i * ACT + a] = V + A[a] - mean;
}

// ---------------------------------------------------------------------------
// Launch
// ---------------------------------------------------------------------------
extern "C" void kernel_launch(void* const* d_in, const int* in_sizes, int n_in,
                              void* d_out, int out_size)
{
    const float *hid, *act, *W_enc, *b_enc, *Wq, *bq, *Wk, *bk, *Wv, *bv;
    const float *Wiq, *biq, *Wik, *bik, *Wiv, *biv, *Wo, *bo, *W_O;
    const float *W_val, *b_val, *W_adv, *b_adv;
    const int* state;

    if (n_in >= 3 && in_sizes[2] == 512) {
        // dict order: hidden, action, state, W_enc, b_enc, Wq,bq,Wk,bk,Wv,bv,
        //             Wiq,biq,Wik,bik,Wiv,biv, Wo,bo, W_O, W_val,b_val,W_adv,b_adv
        hid   = (const float*)d_in[0];  act  = (const float*)d_in[1];
        state = (const int*)  d_in[2];
        W_enc = (const float*)d_in[3];  b_enc = (const float*)d_in[4];
        Wq  = (const float*)d_in[5];    bq  = (const float*)d_in[6];
        Wk  = (const float*)d_in[7];    bk  = (const float*)d_in[8];
        Wv  = (const float*)d_in[9];    bv  = (const float*)d_in[10];
        Wiq = (const float*)d_in[11];   biq = (const float*)d_in[12];
        Wik = (const float*)d_in[13];   bik = (const float*)d_in[14];
        Wiv = (const float*)d_in[15];   biv = (const float*)d_in[16];
        Wo  = (const float*)d_in[17];   bo  = (const float*)d_in[18];
        W_O = (const float*)d_in[19];
        W_val = (const float*)d_in[20]; b_val = (const float*)d_in[21];
        W_adv = (const float*)d_in[22]; b_adv = (const float*)d_in[23];
    } else {
        // signature order: ..., W_adv, b_adv, state
        hid   = (const float*)d_in[0];  act  = (const float*)d_in[1];
        W_enc = (const float*)d_in[2];  b_enc = (const float*)d_in[3];
        Wq  = (const float*)d_in[4];    bq  = (const float*)d_in[5];
        Wk  = (const float*)d_in[6];    bk  = (const float*)d_in[7];
        Wv  = (const float*)d_in[8];    bv  = (const float*)d_in[9];
        Wiq = (const float*)d_in[10];   biq = (const float*)d_in[11];
        Wik = (const float*)d_in[12];   bik = (const float*)d_in[13];
        Wiv = (const float*)d_in[14];   biv = (const float*)d_in[15];
        Wo  = (const float*)d_in[16];   bo  = (const float*)d_in[17];
        W_O = (const float*)d_in[18];
        W_val = (const float*)d_in[19]; b_val = (const float*)d_in[20];
        W_adv = (const float*)d_in[21]; b_adv = (const float*)d_in[22];
        state = (const int*)  d_in[23];
    }

    float* out = (float*)d_out;

    float *g_C_p, *g_P0, *g_P1, *g_P2, *g_Q0, *g_Q1, *g_Q2;
    float *g_S_p, *g_G_p, *g_cnt_p, *g_T_p, *g_h_p;
    cudaGetSymbolAddress((void**)&g_C_p,   g_C);
    cudaGetSymbolAddress((void**)&g_P0,    g_P);
    g_P1 = g_P0 + NA * EE; g_P2 = g_P1 + NA * EE;
    cudaGetSymbolAddress((void**)&g_Q0,    g_QKV);
    g_Q1 = g_Q0 + NA * EE; g_Q2 = g_Q1 + NA * EE;
    cudaGetSymbolAddress((void**)&g_S_p,   g_S);
    cudaGetSymbolAddress((void**)&g_G_p,   g_G);
    cudaGetSymbolAddress((void**)&g_cnt_p, g_cnt);
    cudaGetSymbolAddress((void**)&g_T_p,   g_T);
    cudaGetSymbolAddress((void**)&g_h_p,   g_h);

    // 1. setup
    setup_kernel<<<1, NA>>>(hid, act, state, W_enc, b_enc);

    // 2. outer projections: P = C @ W* + b*   [256,144]@[144,576]
    dim3 gP(EE / 64, NA / 64);
    gemm_k<<<gP, 256>>>(g_C_p, DD, Wq, EE, bq, nullptr, g_P0, EE, NA, EE, DD);
    gemm_k<<<gP, 256>>>(g_C_p, DD, Wk, EE, bk, nullptr, g_P1, EE, NA, EE, DD);
    gemm_k<<<gP, 256>>>(g_C_p, DD, Wv, EE, bv, nullptr, g_P2, EE, NA, EE, DD);

    // 3. inner projections: q = P @ Wi* + bi*  [256,576]@[576,576]
    gemm_k<<<gP, 256>>>(g_P0, EE, Wiq, EE, biq, nullptr, g_Q0, EE, NA, EE, EE);
    gemm_k<<<gP, 256>>>(g_P1, EE, Wik, EE, bik, nullptr, g_Q1, EE, NA, EE, EE);
    gemm_k<<<gP, 256>>>(g_P2, EE, Wiv, EE, biv, nullptr, g_Q2, EE, NA, EE, EE);

    // 4. S[h] = scale * q2_h @ k2_h^T
    const float scale = 1.0f / sqrtf((float)HDH);
    dim3 gS(NA / 64, NA / 64, NH);
    gemm_nt_heads<<<gS, 256>>>(g_Q0, g_Q1, g_S_p, scale);

    // 5. per-agent masked softmax-sum + sparse context
    attn_kernel<<<NA, 128>>>(g_Q2);

    // 6. T = G @ Wo_proj + cnt * bo_proj
    gemm_k<<<gP, 256>>>(g_G_p, EE, Wo, EE, bo, g_cnt_p, g_T_p, EE, NA, EE, EE);

    // 7. h = T @ W_O   [256,576]@[576,144]
    dim3 gH((DD + 63) / 64, NA / 64);
    gemm_k<<<gH, 256>>>(g_T_p, EE, W_O, DD, nullptr, nullptr, g_h_p, DD, NA, DD, EE);

    // 8. dueling head
    final_kernel<<<1, NA>>>(W_val, b_val, W_adv, b_adv, out);
}

// round 2
// speedup vs baseline: 1.0055x; 1.0055x over previous
#include <cuda_runtime.h>
#include <math.h>

// ---------------------------------------------------------------------------
// Problem constants
// ---------------------------------------------------------------------------
#define NA   256      // num agents
#define HID  128
#define ACT  5
#define NH   4
#define DD   144      // concat dim
#define EE   576      // embed dim
#define HDH  144      // per-head dim
#define OBS_RX 4
#define OBS_RY 2

#define WC_ROWS 145   // 144 combined-weight rows + 1 combined-bias row

// ---------------------------------------------------------------------------
// Device scratch
// ---------------------------------------------------------------------------
__device__ float    g_C[NA * DD];               // concat features
__device__ unsigned g_mask[NA * 8];             // bitmask rows
__device__ float    g_Wc[3][WC_ROWS * EE];      // combined proj weights (+bias row)
__device__ float    g_Q[3][NA * EE];            // q2,k2,v2
__device__ float    g_S[NH * NA * NA];          // shared scores per head
__device__ float    g_G[NA * EE];               // masked-context sums
__device__ float    g_cnt[NA];                  // |J_i|
__device__ float    g_Wfin[EE * 6];             // Wo_proj @ W_O @ [W_val|W_adv]
__device__ float    g_bfin[6];                  // bo_proj @ W_O @ [W_val|W_adv]

// ---------------------------------------------------------------------------
// Setup: mask bits + C = [obs_encoder(hidden), action]
// ---------------------------------------------------------------------------
__global__ void setup_kernel(const float* __restrict__ hid,
                             const float* __restrict__ act,
                             const int*   __restrict__ state,
                             const float* __restrict__ W_enc,
                             const float* __restrict__ b_enc)
{
    __shared__ int px[NA], py[NA];
    int i = threadIdx.x;
    px[i] = state[2 * i];
    py[i] = state[2 * i + 1];
    __syncthreads();

    unsigned w[8] = {0, 0, 0, 0, 0, 0, 0, 0};
    int xi = px[i], yi = py[i];
    for (int j = i + 1; j < NA; ++j) {
        int dx = abs(xi - px[j]);
        int dy = abs(yi - py[j]);
        if (dx <= OBS_RX && dy <= OBS_RY) w[j >> 5] |= (1u << (j & 31));
    }
#pragma unroll
    for (int t = 0; t < 8; ++t) g_mask[i * 8 + t] = w[t];

    float o[16];
#pragma unroll
    for (int t = 0; t < 16; ++t) o[t] = b_enc[t];
    for (int d = 0; d < HID; ++d) {
        float hv = hid[i * HID + d];
#pragma unroll
        for (int t = 0; t < 16; ++t) o[t] += hv * W_enc[d * 16 + t];
    }
#pragma unroll
    for (int t = 0; t < 16; ++t) g_C[i * DD + t] = o[t];
    for (int d = 0; d < HID; ++d) g_C[i * DD + 16 + d] = act[i * HID + d];
}

// ---------------------------------------------------------------------------
// Weight combine: g_Wc[z] = [Wz; bz] @ Wiz, row 144 += biz.
// M=145 (guarded), N=576, K=576. z in {q,k,v}. Grid (9, 3, 3), 256 threads.
// ---------------------------------------------------------------------------
__global__ __launch_bounds__(256)
void combine_gemm(const float* __restrict__ Wq, const float* __restrict__ bq,
                  const float* __restrict__ Wk, const float* __restrict__ bk,
                  const float* __restrict__ Wv, const float* __restrict__ bv,
                  const float* __restrict__ Wiq, const float* __restrict__ biq,
                  const float* __restrict__ Wik, const float* __restrict__ bik,
                  const float* __restrict__ Wiv, const float* __restrict__ biv)
{
    __shared__ float As[16][68];
    __shared__ float Bs[16][68];

    const int z = blockIdx.z;
    const float* A    = (z == 0) ? Wq : (z == 1) ? Wk : Wv;     // [144,576]
    const float* arow = (z == 0) ? bq : (z == 1) ? bk : bv;     // [576]
    const float* B    = (z == 0) ? Wiq : (z == 1) ? Wik : Wiv;  // [576,576]
    const float* bias = (z == 0) ? biq : (z == 1) ? bik : biv;  // [576]
    float* C = &g_Wc[z][0];

    const int tid = threadIdx.x;
    const int tx  = tid & 15;
    const int ty  = tid >> 4;
    const int m0  = blockIdx.y * 64;
    const int n0  = blockIdx.x * 64;

    float acc[4][4];
#pragma unroll
    for (int i = 0; i < 4; ++i)
#pragma unroll
        for (int j = 0; j < 4; ++j) acc[i][j] = 0.f;

    for (int k0 = 0; k0 < EE; k0 += 16) {
        // A tile 64x16 with row guard (rows 0..143 = W, 144 = bias row, rest 0)
        {
            int m = tid >> 2;
            int k = (tid & 3) * 4;
            int r = m0 + m;
            float4 v;
            if (r < DD)       v = *reinterpret_cast<const float4*>(&A[r * EE + k0 + k]);
            else if (r == DD) v = *reinterpret_cast<const float4*>(&arow[k0 + k]);
            else              v = make_float4(0.f, 0.f, 0.f, 0.f);
            As[k + 0][m] = v.x; As[k + 1][m] = v.y;
            As[k + 2][m] = v.z; As[k + 3][m] = v.w;
        }
        {
            int k = tid >> 4;
            int n = (tid & 15) * 4;
            float4 v = *reinterpret_cast<const float4*>(&B[(k0 + k) * EE + n0 + n]);
            Bs[k][n + 0] = v.x; Bs[k][n + 1] = v.y;
            Bs[k][n + 2] = v.z; Bs[k][n + 3] = v.w;
        }
        __syncthreads();
#pragma unroll
        for (int kk = 0; kk < 16; ++kk) {
            float a[4], b[4];
#pragma unroll
            for (int i = 0; i < 4; ++i) a[i] = As[kk][ty * 4 + i];
#pragma unroll
            for (int j = 0; j < 4; ++j) b[j] = Bs[kk][tx * 4 + j];
#pragma unroll
            for (int i = 0; i < 4; ++i)
#pragma unroll
                for (int j = 0; j < 4; ++j) acc[i][j] += a[i] * b[j];
        }
        __syncthreads();
    }

#pragma unroll
    for (int i = 0; i < 4; ++i) {
        int m = m0 + ty * 4 + i;
        if (m >= WC_ROWS) continue;
#pragma unroll
        for (int j = 0; j < 4; ++j) {
            int n = n0 + tx * 4 + j;
            float v = acc[i][j];
            if (m == DD) v += bias[n];
            C[m * EE + n] = v;
        }
    }
}

// ---------------------------------------------------------------------------
// Head combine: W2 = W_O @ [W_val | W_adv]  ([576,6]),
// Wfin = Wo_proj @ W2, bfin = bo_proj @ W2.  Grid 9 blocks x 128 threads.
// ---------------------------------------------------------------------------
__global__ __launch_bounds__(128)
void headcombine_kernel(const float* __restrict__ Wo_proj,
                        const float* __restrict__ bo,
                        const float* __restrict__ W_O,
                        const float* __restrict__ W_val,
                        const float* __restrict__ W_adv)
{
    __shared__ float sW2[EE * 6];
    const int tid = threadIdx.x;

    // phase 1: every block computes full W2 (redundant, tiny)
    for (int r = tid; r < EE; r += 128) {
        float a[6];
#pragma unroll
        for (int j = 0; j < 6; ++j) a[j] = 0.f;
        for (int k = 0; k < DD; ++k) {
            float w = W_O[r * DD + k];
            a[0] += w * W_val[k];
#pragma unroll
            for (int j = 0; j < ACT; ++j) a[1 + j] += w * W_adv[k * ACT + j];
        }
#pragma unroll
        for (int j = 0; j < 6; ++j) sW2[r * 6 + j] = a[j];
    }
    __syncthreads();

    // phase 2: 64 rows of Wfin per block
    if (tid < 64) {
        int e = blockIdx.x * 64 + tid;
        float a[6];
#pragma unroll
        for (int j = 0; j < 6; ++j) a[j] = 0.f;
        for (int f = 0; f < EE; ++f) {
            float w = Wo_proj[e * EE + f];
#pragma unroll
            for (int j = 0; j < 6; ++j) a[j] += w * sW2[f * 6 + j];
        }
#pragma unroll
        for (int j = 0; j < 6; ++j) g_Wfin[e * 6 + j] = a[j];
    } else if (blockIdx.x == 0 && tid < 70) {
        int j = tid - 64;
        float a = 0.f;
        for (int f = 0; f < EE; ++f) a += bo[f] * sW2[f * 6 + j];
        g_bfin[j] = a;
    }
}

// ---------------------------------------------------------------------------
// QKV projection: g_Q[z] = g_C @ g_Wc[z][0:144] + g_Wc[z][144]
// M=256, K=144, N=576. Grid (9, 4, 3), 256 threads.
// ---------------------------------------------------------------------------
__global__ __launch_bounds__(256)
void qkv_gemm()
{
    __shared__ float As[16][68];
    __shared__ float Bs[16][68];

    const int z = blockIdx.z;
    const float* B    = &g_Wc[z][0];
    const float* bias = &g_Wc[z][DD * EE];
    float* C = &g_Q[z][0];

    const int tid = threadIdx.x;
    const int tx  = tid & 15;
    const int ty  = tid >> 4;
    const int m0  = blockIdx.y * 64;
    const int n0  = blockIdx.x * 64;

    float acc[4][4];
#pragma unroll
    for (int i = 0; i < 4; ++i)
#pragma unroll
        for (int j = 0; j < 4; ++j) acc[i][j] = 0.f;

    for (int k0 = 0; k0 < DD; k0 += 16) {
        {
            int m = tid >> 2;
            int k = (tid & 3) * 4;
            float4 v = *reinterpret_cast<const float4*>(&g_C[(m0 + m) * DD + k0 + k]);
            As[k + 0][m] = v.x; As[k + 1][m] = v.y;
            As[k + 2][m] = v.z; As[k + 3][m] = v.w;
        }
        {
            int k = tid >> 4;
            int n = (tid & 15) * 4;
            float4 v = *reinterpret_cast<const float4*>(&B[(k0 + k) * EE + n0 + n]);
            Bs[k][n + 0] = v.x; Bs[k][n + 1] = v.y;
            Bs[k][n + 2] = v.z; Bs[k][n + 3] = v.w;
        }
        __syncthreads();
#pragma unroll
        for (int kk = 0; kk < 16; ++kk) {
            float a[4], b[4];
#pragma unroll
            for (int i = 0; i < 4; ++i) a[i] = As[kk][ty * 4 + i];
#pragma unroll
            for (int j = 0; j < 4; ++j) b[j] = Bs[kk][tx * 4 + j];
#pragma unroll
            for (int i = 0; i < 4; ++i)
#pragma unroll
                for (int j = 0; j < 4; ++j) acc[i][j] += a[i] * b[j];
        }
        __syncthreads();
    }

#pragma unroll
    for (int i = 0; i < 4; ++i) {
        int m = m0 + ty * 4 + i;
#pragma unroll
        for (int j = 0; j < 4; ++j) {
            int n = n0 + tx * 4 + j;
            C[m * EE + n] = acc[i][j] + bias[n];
        }
    }
}

// ---------------------------------------------------------------------------
// S[h] = scale * q2_h @ k2_h^T. Grid (4, 4, 4), 256 threads.
// ---------------------------------------------------------------------------
__global__ __launch_bounds__(256)
void gemm_nt_heads(float scale)
{
    __shared__ float As[16][68];
    __shared__ float Bs[16][68];

    const int h   = blockIdx.z;
    const float* A = &g_Q[0][0] + h * HDH;   // lda = EE
    const float* B = &g_Q[1][0] + h * HDH;
    float* C = g_S + h * NA * NA;

    const int tid = threadIdx.x;
    const int tx  = tid & 15;
    const int ty  = tid >> 4;
    const int m0  = blockIdx.y * 64;
    const int n0  = blockIdx.x * 64;

    float acc[4][4];
#pragma unroll
    for (int i = 0; i < 4; ++i)
#pragma unroll
        for (int j = 0; j < 4; ++j) acc[i][j] = 0.f;

    for (int k0 = 0; k0 < HDH; k0 += 16) {
        {
            int m = tid >> 2;
            int k = (tid & 3) * 4;
            float4 v = *reinterpret_cast<const float4*>(&A[(m0 + m) * EE + k0 + k]);
            As[k + 0][m] = v.x; As[k + 1][m] = v.y;
            As[k + 2][m] = v.z; As[k + 3][m] = v.w;
        }
        {
            int m = tid >> 2;
            int k = (tid & 3) * 4;
            float4 v = *reinterpret_cast<const float4*>(&B[(n0 + m) * EE + k0 + k]);
            Bs[k + 0][m] = v.x; Bs[k + 1][m] = v.y;
            Bs[k + 2][m] = v.z; Bs[k + 3][m] = v.w;
        }
        __syncthreads();
#pragma unroll
        for (int kk = 0; kk < 16; ++kk) {
            float a[4], b[4];
#pragma unroll
            for (int i = 0; i < 4; ++i) a[i] = As[kk][ty * 4 + i];
#pragma unroll
            for (int j = 0; j < 4; ++j) b[j] = Bs[kk][tx * 4 + j];
#pragma unroll
            for (int i = 0; i < 4; ++i)
#pragma unroll
                for (int j = 0; j < 4; ++j) acc[i][j] += a[i] * b[j];
        }
        __syncthreads();
    }

#pragma unroll
    for (int i = 0; i < 4; ++i) {
        int m = m0 + ty * 4 + i;
#pragma unroll
        for (int j = 0; j < 4; ++j) {
            int n = n0 + tx * 4 + j;
            C[m * NA + n] = scale * acc[i][j];
        }
    }
}

// ---------------------------------------------------------------------------
// Per-agent masked softmax-sum + sparse context: G, cnt.
// ---------------------------------------------------------------------------
__global__ void attn_kernel()
{
    const int i   = blockIdx.x;
    const int tid = threadIdx.x;
    const float* v2 = &g_Q[2][0];

    __shared__ int   Jl[NA];
    __shared__ int   sn;
    __shared__ float w[NH * NA];

    if (tid == 0) {
        int n = 0;
        for (int t = 0; t < 8; ++t) {
            unsigned bits = g_mask[i * 8 + t];
            while (bits) {
                int b = __ffs(bits) - 1;
                Jl[n++] = t * 32 + b;
                bits &= bits - 1;
            }
        }
        sn = n;
        g_cnt[i] = (float)n;
    }
    for (int t = tid; t < NH * NA; t += blockDim.x) w[t] = 0.f;
    __syncthreads();

    const int n = sn;
    if (n == 0) {
        for (int e = tid; e < EE; e += blockDim.x) g_G[i * EE + e] = 0.f;
        return;
    }

    for (int p = tid; p < NH * n; p += blockDim.x) {
        int h  = p & 3;
        int jj = Jl[p >> 2];
        const float* row = g_S + h * NA * NA + jj * NA;
        float m = -1e30f;
        for (int t = 0; t < n; ++t) m = fmaxf(m, row[Jl[t]]);
        float sum = 0.f;
        for (int t = 0; t < n; ++t) sum += expf(row[Jl[t]] - m);
        float inv = 1.f / sum;
        for (int t = 0; t < n; ++t)
            atomicAdd(&w[h * NA + t], expf(row[Jl[t]] - m) * inv);
    }
    __syncthreads();

    for (int e = tid; e < EE; e += blockDim.x) {
        int h = e / HDH;
        float acc = 0.f;
        for (int t = 0; t < n; ++t)
            acc += w[h * NA + t] * v2[Jl[t] * EE + e];
        g_G[i * EE + e] = acc;
    }
}

// ---------------------------------------------------------------------------
// Final: Q[i,:] from G[i,:] @ Wfin + cnt*bfin + biases, dueling combine.
// One block, 256 threads (thread = agent).
// ---------------------------------------------------------------------------
__global__ __launch_bounds__(256)
void final_kernel(const float* __restrict__ b_val,
                  const float* __restrict__ b_adv,
                  float* __restrict__ out)
{
    __shared__ float sW[EE * 6];
    const int i = threadIdx.x;
    for (int t = i; t < EE * 6; t += 256) sW[t] = g_Wfin[t];
    __syncthreads();

    const float* Gr = g_G + i * EE;
    float a[6];
#pragma unroll
    for (int j = 0; j < 6; ++j) a[j] = 0.f;
    for (int d = 0; d < EE; d += 4) {
        float4 g = *reinterpret_cast<const float4*>(&Gr[d]);
#pragma unroll
        for (int j = 0; j < 6; ++j) {
            a[j] += g.x * sW[(d + 0) * 6 + j];
            a[j] += g.y * sW[(d + 1) * 6 + j];
            a[j] += g.z * sW[(d + 2) * 6 + j];
            a[j] += g.w * sW[(d + 3) * 6 + j];
        }
    }
    float c = g_cnt[i];
    float V = a[0] + c * g_bfin[0] + b_val[0];
    float A[ACT], mean = 0.f;
#pragma unroll
    for (int j = 0; j < ACT; ++j) {
        A[j] = a[1 + j] + c * g_bfin[1 + j] + b_adv[j];
        mean += A[j];
    }
    mean *= (1.f / ACT);
#pragma unroll
    for (int j = 0; j < ACT; ++j) out[i * ACT + j] = V + A[j] - mean;
}

// ---------------------------------------------------------------------------
// Launch
// ---------------------------------------------------------------------------
extern "C" void kernel_launch(void* const* d_in, const int* in_sizes, int n_in,
                              void* d_out, int out_size)
{
    const float *hid, *act, *W_enc, *b_enc, *Wq, *bq, *Wk, *bk, *Wv, *bv;
    const float *Wiq, *biq, *Wik, *bik, *Wiv, *biv, *Wo, *bo, *W_O;
    const float *W_val, *b_val, *W_adv, *b_adv;
    const int* state;

    if (n_in >= 3 && in_sizes[2] == 512) {
        hid   = (const float*)d_in[0];  act  = (const float*)d_in[1];
        state = (const int*)  d_in[2];
        W_enc = (const float*)d_in[3];  b_enc = (const float*)d_in[4];
        Wq  = (const float*)d_in[5];    bq  = (const float*)d_in[6];
        Wk  = (const float*)d_in[7];    bk  = (const float*)d_in[8];
        Wv  = (const float*)d_in[9];    bv  = (const float*)d_in[10];
        Wiq = (const float*)d_in[11];   biq = (const float*)d_in[12];
        Wik = (const float*)d_in[13];   bik = (const float*)d_in[14];
        Wiv = (const float*)d_in[15];   biv = (const float*)d_in[16];
        Wo  = (const float*)d_in[17];   bo  = (const float*)d_in[18];
        W_O = (const float*)d_in[19];
        W_val = (const float*)d_in[20]; b_val = (const float*)d_in[21];
        W_adv = (const float*)d_in[22]; b_adv = (const float*)d_in[23];
    } else {
        hid   = (const float*)d_in[0];  act  = (const float*)d_in[1];
        W_enc = (const float*)d_in[2];  b_enc = (const float*)d_in[3];
        Wq  = (const float*)d_in[4];    bq  = (const float*)d_in[5];
        Wk  = (const float*)d_in[6];    bk  = (const float*)d_in[7];
        Wv  = (const float*)d_in[8];    bv  = (const float*)d_in[9];
        Wiq = (const float*)d_in[10];   biq = (const float*)d_in[11];
        Wik = (const float*)d_in[12];   bik = (const float*)d_in[13];
        Wiv = (const float*)d_in[14];   biv = (const float*)d_in[15];
        Wo  = (const float*)d_in[16];   bo  = (const float*)d_in[17];
        W_O = (const float*)d_in[18];
        W_val = (const float*)d_in[19]; b_val = (const float*)d_in[20];
        W_adv = (const float*)d_in[21]; b_adv = (const float*)d_in[22];
        state = (const int*)  d_in[23];
    }

    float* out = (float*)d_out;

    // 1. setup (mask + C)
    setup_kernel<<<1, NA>>>(hid, act, state, W_enc, b_enc);

    // 2. combined projection weights (independent of setup)
    combine_gemm<<<dim3(EE / 64, 3, 3), 256>>>(Wq, bq, Wk, bk, Wv, bv,
                                               Wiq, biq, Wik, bik, Wiv, biv);

    // 3. combined output-head weights (independent, only needed by final)
    headcombine_kernel<<<EE / 64, 128>>>(Wo, bo, W_O, W_val, W_adv);

    // 4. q,k,v = C @ Wc + bc
    qkv_gemm<<<dim3(EE / 64, NA / 64, 3), 256>>>();

    // 5. S[h] = scale * q2_h @ k2_h^T
    gemm_nt_heads<<<dim3(NA / 64, NA / 64, NH), 256>>>(1.0f / sqrtf((float)HDH));

    // 6. masked softmax-sum + sparse context
    attn_kernel<<<NA, 128>>>();

    // 7. final head
    final_kernel<<<1, 256>>>(b_val, b_adv, out);
}

// round 3
// speedup vs baseline: 2.5262x; 2.5124x over previous
#include <cuda_runtime.h>
#include <math.h>

// ---------------------------------------------------------------------------
// Problem constants
// ---------------------------------------------------------------------------
#define NA   256
#define HID  128
#define ACT  5
#define NH   4
#define DD   144
#define EE   576
#define HDH  144
#define OBS_RX 4
#define OBS_RY 2
#define WC_ROWS 145
#define NB   148          // persistent grid size (<= SM count)

// ---------------------------------------------------------------------------
// Device scratch
// ---------------------------------------------------------------------------
__device__ float    g_C[NA * DD];
__device__ unsigned g_mask[NA * 8];
__device__ float    g_Wc[3][WC_ROWS * EE];
__device__ float    g_Q[3][NA * EE];
__device__ float    g_S[NH * NA * NA];
__device__ float    g_G[NA * EE];
__device__ float    g_cnt[NA];
__device__ float    g_Wfin[EE * 6];
__device__ float    g_bfin[6];

// grid barrier state (count returns to 0 after each barrier; sense flips an
// EVEN number of times per launch, so state is identical across graph replays)
__device__ unsigned          g_bar_count;
__device__ volatile unsigned g_bar_sense;

// ---------------------------------------------------------------------------
// Shared memory union (stages never overlap within a block)
// ---------------------------------------------------------------------------
struct SmemGemm  { float As[2][16][68]; float Bs[2][16][68]; };
struct SmemAttn  { float w[NH * NA]; int Jl[NA]; int sn; };
struct SmemHead  { float W2[EE * 6]; };
struct SmemSetup { int px[NA]; int py[NA]; };
union  SmemU { SmemGemm g; SmemAttn a; SmemHead h; SmemSetup s; };

// ---------------------------------------------------------------------------
// 16-deep k-slab MMA from shared tiles
// ---------------------------------------------------------------------------
__device__ __forceinline__ void mma16(const float (*As)[68], const float (*Bs)[68],
                                      int ty, int tx, float acc[4][4])
{
#pragma unroll
    for (int kk = 0; kk < 16; ++kk) {
        float a[4], b[4];
#pragma unroll
        for (int i = 0; i < 4; ++i) a[i] = As[kk][ty * 4 + i];
#pragma unroll
        for (int j = 0; j < 4; ++j) b[j] = Bs[kk][tx * 4 + j];
#pragma unroll
        for (int i = 0; i < 4; ++i)
#pragma unroll
            for (int j = 0; j < 4; ++j) acc[i][j] += a[i] * b[j];
    }
}

#define GRID_BAR()                                                        \
    do {                                                                  \
        __threadfence();                                                  \
        __syncthreads();                                                  \
        if (tid == 0) {                                                   \
            unsigned target = s_sense ^ 1u;                               \
            s_sense = target;                                             \
            unsigned aidx = atomicAdd(&g_bar_count, 1u);                  \
            if (aidx == (unsigned)(NB - 1)) {                             \
                g_bar_count = 0u;                                         \
                __threadfence();                                          \
                g_bar_sense = target;                                     \
            } else {                                                      \
                while (g_bar_sense != target) __nanosleep(64);            \
            }                                                             \
        }                                                                 \
        __syncthreads();                                                  \
    } while (0)

// ---------------------------------------------------------------------------
// The single fused kernel
// ---------------------------------------------------------------------------
__global__ __launch_bounds__(256)
void fused_kernel(const float* __restrict__ hid,   const float* __restrict__ act,
                  const int*   __restrict__ state,
                  const float* __restrict__ W_enc, const float* __restrict__ b_enc,
                  const float* __restrict__ Wq,  const float* __restrict__ bq,
                  const float* __restrict__ Wk,  const float* __restrict__ bk,
                  const float* __restrict__ Wv,  const float* __restrict__ bv,
                  const float* __restrict__ Wiq, const float* __restrict__ biq,
                  const float* __restrict__ Wik, const float* __restrict__ bik,
                  const float* __restrict__ Wiv, const float* __restrict__ biv,
                  const float* __restrict__ Wo,  const float* __restrict__ bo,
                  const float* __restrict__ W_O,
                  const float* __restrict__ W_val, const float* __restrict__ b_val,
                  const float* __restrict__ W_adv, const float* __restrict__ b_adv,
                  float* __restrict__ out)
{
    __shared__ SmemU sm;
    __shared__ unsigned s_sense;
    const int tid = threadIdx.x;
    const int bx  = blockIdx.x;
    if (tid == 0) s_sense = 0u;

    // common GEMM thread indexing
    const int tx  = tid & 15;          // n quad
    const int ty  = tid >> 4;          // m quad
    const int ma  = tid >> 2;          // row for A-style tile load
    const int ka  = (tid & 3) * 4;     // k offset for A-style tile load
    const int kb  = tid >> 4;          // k row for B-style tile load
    const int nbv = (tid & 15) * 4;    // n offset for B-style tile load

    // =====================================================================
    // STAGE A (parallel tasks):
    //   bx   0..80 : combined proj weights  g_Wc[z] = [Wz;bz] @ Wiz (+biz row)
    //   bx  81..89 : head combine           g_Wfin, g_bfin
    //   bx  90..97 : obs encoder + action copy -> g_C (32 agents each)
    //   bx  ==  98 : visibility mask bits
    // =====================================================================
    if (bx < 81) {
        const int z  = bx / 27, r = bx % 27;
        const int m0 = (r / 9) * 64, n0 = (r % 9) * 64;
        const float* Az   = (z == 0) ? Wq  : (z == 1) ? Wk  : Wv;
        const float* brow = (z == 0) ? bq  : (z == 1) ? bk  : bv;
        const float* Bz   = (z == 0) ? Wiq : (z == 1) ? Wik : Wiv;
        const float* bi   = (z == 0) ? biq : (z == 1) ? bik : biv;
        float* Cd = &g_Wc[z][0];

        float acc[4][4] = {};
        const int rA = m0 + ma;
        float4 va, vb;
        // prefetch k-tile 0
        if (rA < DD)       va = *(const float4*)&Az[rA * EE + ka];
        else if (rA == DD) va = *(const float4*)&brow[ka];
        else               va = make_float4(0.f, 0.f, 0.f, 0.f);
        vb = *(const float4*)&Bz[kb * EE + n0 + nbv];
        sm.g.As[0][ka + 0][ma] = va.x; sm.g.As[0][ka + 1][ma] = va.y;
        sm.g.As[0][ka + 2][ma] = va.z; sm.g.As[0][ka + 3][ma] = va.w;
        sm.g.Bs[0][kb][nbv + 0] = vb.x; sm.g.Bs[0][kb][nbv + 1] = vb.y;
        sm.g.Bs[0][kb][nbv + 2] = vb.z; sm.g.Bs[0][kb][nbv + 3] = vb.w;
        __syncthreads();

        const int nk = EE / 16;   // 36
        for (int it = 0; it < nk; ++it) {
            const int buf = it & 1;
            if (it + 1 < nk) {
                const int k0 = (it + 1) * 16;
                if (rA < DD)       va = *(const float4*)&Az[rA * EE + k0 + ka];
                else if (rA == DD) va = *(const float4*)&brow[k0 + ka];
                else               va = make_float4(0.f, 0.f, 0.f, 0.f);
                vb = *(const float4*)&Bz[(k0 + kb) * EE + n0 + nbv];
            }
            mma16(sm.g.As[buf], sm.g.Bs[buf], ty, tx, acc);
            if (it + 1 < nk) {
                const int nb2 = buf ^ 1;
                sm.g.As[nb2][ka + 0][ma] = va.x; sm.g.As[nb2][ka + 1][ma] = va.y;
                sm.g.As[nb2][ka + 2][ma] = va.z; sm.g.As[nb2][ka + 3][ma] = va.w;
                sm.g.Bs[nb2][kb][nbv + 0] = vb.x; sm.g.Bs[nb2][kb][nbv + 1] = vb.y;
                sm.g.Bs[nb2][kb][nbv + 2] = vb.z; sm.g.Bs[nb2][kb][nbv + 3] = vb.w;
            }
            __syncthreads();
        }
#pragma unroll
        for (int i = 0; i < 4; ++i) {
            const int m = m0 + ty * 4 + i;
            if (m >= WC_ROWS) continue;
#pragma unroll
            for (int j = 0; j < 4; ++j) {
                const int n = n0 + tx * 4 + j;
                float v = acc[i][j];
                if (m == DD) v += bi[n];
                Cd[m * EE + n] = v;
            }
        }
    } else if (bx < 90) {
        // ---- head combine: W2 = W_O @ [W_val|W_adv]; Wfin = Wo @ W2 ----
        for (int r = tid; r < EE; r += 256) {
            float a[6] = {};
            for (int k = 0; k < DD; ++k) {
                const float w = W_O[r * DD + k];
                a[0] += w * W_val[k];
#pragma unroll
                for (int j = 0; j < ACT; ++j) a[1 + j] += w * W_adv[k * ACT + j];
            }
#pragma unroll
            for (int j = 0; j < 6; ++j) sm.h.W2[r * 6 + j] = a[j];
        }
        __syncthreads();
        if (tid < 64) {
            const int e = (bx - 81) * 64 + tid;
            float a[6] = {};
            for (int f = 0; f < EE; ++f) {
                const float w = Wo[e * EE + f];
#pragma unroll
                for (int j = 0; j < 6; ++j) a[j] += w * sm.h.W2[f * 6 + j];
            }
#pragma unroll
            for (int j = 0; j < 6; ++j) g_Wfin[e * 6 + j] = a[j];
        } else if (bx == 81 && tid < 70) {
            const int j = tid - 64;
            float s = 0.f;
            for (int f = 0; f < EE; ++f) s += bo[f] * sm.h.W2[f * 6 + j];
            g_bfin[j] = s;
        }
    } else if (bx < 98) {
        // ---- obs encoder (32 agents per block) + action copy ----
        const int base  = (bx - 90) * 32;
        const int ai    = base + (tid >> 3);
        const int tgrp  = (tid & 7) * 2;
        float o0 = b_enc[tgrp], o1 = b_enc[tgrp + 1];
        for (int d = 0; d < HID; ++d) {
            const float hv = hid[ai * HID + d];
            o0 += hv * W_enc[d * 16 + tgrp];
            o1 += hv * W_enc[d * 16 + tgrp + 1];
        }
        g_C[ai * DD + tgrp]     = o0;
        g_C[ai * DD + tgrp + 1] = o1;
        const float4* act4 = (const float4*)act;
        for (int idx = tid; idx < 32 * 32; idx += 256) {
            const int row = idx >> 5, col = idx & 31;
            *(float4*)&g_C[(base + row) * DD + 16 + col * 4] =
                act4[(base + row) * 32 + col];
        }
    } else if (bx == 98) {
        // ---- visibility mask ----
        const int i = tid;
        sm.s.px[i] = state[2 * i];
        sm.s.py[i] = state[2 * i + 1];
        __syncthreads();
        unsigned wbits[8] = {0, 0, 0, 0, 0, 0, 0, 0};
        const int xi = sm.s.px[i], yi = sm.s.py[i];
        for (int j = i + 1; j < NA; ++j) {
            const int dx = abs(xi - sm.s.px[j]);
            const int dy = abs(yi - sm.s.py[j]);
            if (dx <= OBS_RX && dy <= OBS_RY) wbits[j >> 5] |= (1u << (j & 31));
        }
#pragma unroll
        for (int t = 0; t < 8; ++t) g_mask[i * 8 + t] = wbits[t];
    }
    GRID_BAR();

    // =====================================================================
    // STAGE B: q,k,v = C @ Wc + bias-row    (108 tiles)
    // =====================================================================
    if (bx < 108) {
        const int z  = bx / 36, r = bx % 36;
        const int m0 = (r / 9) * 64, n0 = (r % 9) * 64;
        const float* B    = &g_Wc[z][0];
        const float* bias = &g_Wc[z][DD * EE];
        float* Cd = &g_Q[z][0];

        float acc[4][4] = {};
        float4 va, vb;
        va = *(const float4*)&g_C[(m0 + ma) * DD + ka];
        vb = *(const float4*)&B[kb * EE + n0 + nbv];
        sm.g.As[0][ka + 0][ma] = va.x; sm.g.As[0][ka + 1][ma] = va.y;
        sm.g.As[0][ka + 2][ma] = va.z; sm.g.As[0][ka + 3][ma] = va.w;
        sm.g.Bs[0][kb][nbv + 0] = vb.x; sm.g.Bs[0][kb][nbv + 1] = vb.y;
        sm.g.Bs[0][kb][nbv + 2] = vb.z; sm.g.Bs[0][kb][nbv + 3] = vb.w;
        __syncthreads();

        const int nk = DD / 16;   // 9
        for (int it = 0; it < nk; ++it) {
            const int buf = it & 1;
            if (it + 1 < nk) {
                const int k0 = (it + 1) * 16;
                va = *(const float4*)&g_C[(m0 + ma) * DD + k0 + ka];
                vb = *(const float4*)&B[(k0 + kb) * EE + n0 + nbv];
            }
            mma16(sm.g.As[buf], sm.g.Bs[buf], ty, tx, acc);
            if (it + 1 < nk) {
                const int nb2 = buf ^ 1;
                sm.g.As[nb2][ka + 0][ma] = va.x; sm.g.As[nb2][ka + 1][ma] = va.y;
                sm.g.As[nb2][ka + 2][ma] = va.z; sm.g.As[nb2][ka + 3][ma] = va.w;
                sm.g.Bs[nb2][kb][nbv + 0] = vb.x; sm.g.Bs[nb2][kb][nbv + 1] = vb.y;
                sm.g.Bs[nb2][kb][nbv + 2] = vb.z; sm.g.Bs[nb2][kb][nbv + 3] = vb.w;
            }
            __syncthreads();
        }
#pragma unroll
        for (int i = 0; i < 4; ++i) {
            const int m = m0 + ty * 4 + i;
#pragma unroll
            for (int j = 0; j < 4; ++j) {
                const int n = n0 + tx * 4 + j;
                Cd[m * EE + n] = acc[i][j] + bias[n];
            }
        }
    }
    GRID_BAR();

    // =====================================================================
    // STAGE C: S[h] = scale * q2_h @ k2_h^T   (64 tiles)
    // =====================================================================
    if (bx < 64) {
        const int h  = bx >> 4;
        const int m0 = ((bx >> 2) & 3) * 64;
        const int n0 = (bx & 3) * 64;
        const float* A = &g_Q[0][0] + h * HDH;
        const float* B = &g_Q[1][0] + h * HDH;
        float* Cd = g_S + h * NA * NA;
        const float scale = 1.0f / 12.0f;

        float acc[4][4] = {};
        float4 va, vb;
        va = *(const float4*)&A[(m0 + ma) * EE + ka];
        vb = *(const float4*)&B[(n0 + ma) * EE + ka];
        sm.g.As[0][ka + 0][ma] = va.x; sm.g.As[0][ka + 1][ma] = va.y;
        sm.g.As[0][ka + 2][ma] = va.z; sm.g.As[0][ka + 3][ma] = va.w;
        sm.g.Bs[0][ka + 0][ma] = vb.x; sm.g.Bs[0][ka + 1][ma] = vb.y;
        sm.g.Bs[0][ka + 2][ma] = vb.z; sm.g.Bs[0][ka + 3][ma] = vb.w;
        __syncthreads();

        const int nk = HDH / 16;   // 9
        for (int it = 0; it < nk; ++it) {
            const int buf = it & 1;
            if (it + 1 < nk) {
                const int k0 = (it + 1) * 16;
                va = *(const float4*)&A[(m0 + ma) * EE + k0 + ka];
                vb = *(const float4*)&B[(n0 + ma) * EE + k0 + ka];
            }
            mma16(sm.g.As[buf], sm.g.Bs[buf], ty, tx, acc);
            if (it + 1 < nk) {
                const int nb2 = buf ^ 1;
                sm.g.As[nb2][ka + 0][ma] = va.x; sm.g.As[nb2][ka + 1][ma] = va.y;
                sm.g.As[nb2][ka + 2][ma] = va.z; sm.g.As[nb2][ka + 3][ma] = va.w;
                sm.g.Bs[nb2][ka + 0][ma] = vb.x; sm.g.Bs[nb2][ka + 1][ma] = vb.y;
                sm.g.Bs[nb2][ka + 2][ma] = vb.z; sm.g.Bs[nb2][ka + 3][ma] = vb.w;
            }
            __syncthreads();
        }
#pragma unroll
        for (int i = 0; i < 4; ++i) {
            const int m = m0 + ty * 4 + i;
#pragma unroll
            for (int j = 0; j < 4; ++j) {
                const int n = n0 + tx * 4 + j;
                Cd[m * NA + n] = scale * acc[i][j];
            }
        }
    }
    GRID_BAR();

    // =====================================================================
    // STAGE D: per-agent masked softmax-sum + sparse context -> G, cnt
    // =====================================================================
    for (int i = bx; i < NA; i += NB) {
        for (int t = tid; t < NH * NA; t += 256) sm.a.w[t] = 0.f;
        if (tid == 0) {
            int n = 0;
            for (int t = 0; t < 8; ++t) {
                unsigned bits = g_mask[i * 8 + t];
                while (bits) {
                    const int b = __ffs(bits) - 1;
                    sm.a.Jl[n++] = t * 32 + b;
                    bits &= bits - 1;
                }
            }
            sm.a.sn = n;
            g_cnt[i] = (float)n;
        }
        __syncthreads();

        const int n = sm.a.sn;
        if (n == 0) {
            for (int e = tid; e < EE; e += 256) g_G[i * EE + e] = 0.f;
        } else {
            for (int p = tid; p < NH * n; p += 256) {
                const int h  = p & 3;
                const int jj = sm.a.Jl[p >> 2];
                const float* row = g_S + h * NA * NA + jj * NA;
                float m = -1e30f;
                for (int t = 0; t < n; ++t) m = fmaxf(m, row[sm.a.Jl[t]]);
                float sum = 0.f;
                for (int t = 0; t < n; ++t) sum += expf(row[sm.a.Jl[t]] - m);
                const float inv = 1.f / sum;
                for (int t = 0; t < n; ++t)
                    atomicAdd(&sm.a.w[h * NA + t], expf(row[sm.a.Jl[t]] - m) * inv);
            }
            __syncthreads();
            const float* v2 = &g_Q[2][0];
            for (int e = tid; e < EE; e += 256) {
                const int h = e / HDH;
                float acc = 0.f;
                for (int t = 0; t < n; ++t)
                    acc += sm.a.w[h * NA + t] * v2[sm.a.Jl[t] * EE + e];
                g_G[i * EE + e] = acc;
            }
        }
        __syncthreads();
    }
    GRID_BAR();

    // =====================================================================
    // STAGE E: warp-per-agent final head
    // =====================================================================
    {
        const int gw   = bx * 8 + (tid >> 5);
        const int lane = tid & 31;
        if (gw < NA) {
            const float* Gr = g_G + gw * EE;
            float a[6] = {};
            for (int d = lane; d < EE; d += 32) {
                const float gv = Gr[d];
                const float* Wr = g_Wfin + d * 6;
#pragma unroll
                for (int j = 0; j < 6; ++j) a[j] += gv * Wr[j];
            }
#pragma unroll
            for (int j = 0; j < 6; ++j)
#pragma unroll
                for (int o = 16; o > 0; o >>= 1)
                    a[j] += __shfl_xor_sync(0xffffffffu, a[j], o);
            const float c = g_cnt[gw];
            const float V = a[0] + c * g_bfin[0] + b_val[0];
            float A[ACT], mean = 0.f;
#pragma unroll
            for (int j = 0; j < ACT; ++j) {
                A[j] = a[1 + j] + c * g_bfin[1 + j] + b_adv[j];
                mean += A[j];
            }
            mean *= (1.f / ACT);
            if (lane < ACT) out[gw * ACT + lane] = V + A[lane] - mean;
        }
    }
}

// ---------------------------------------------------------------------------
// Launch
// ---------------------------------------------------------------------------
extern "C" void kernel_launch(void* const* d_in, const int* in_sizes, int n_in,
                              void* d_out, int out_size)
{
    const float *hid, *act, *W_enc, *b_enc, *Wq, *bq, *Wk, *bk, *Wv, *bv;
    const float *Wiq, *biq, *Wik, *bik, *Wiv, *biv, *Wo, *bo, *W_O;
    const float *W_val, *b_val, *W_adv, *b_adv;
    const int* state;

    if (n_in >= 3 && in_sizes[2] == 512) {
        hid   = (const float*)d_in[0];  act  = (const float*)d_in[1];
        state = (const int*)  d_in[2];
        W_enc = (const float*)d_in[3];  b_enc = (const float*)d_in[4];
        Wq  = (const float*)d_in[5];    bq  = (const float*)d_in[6];
        Wk  = (const float*)d_in[7];    bk  = (const float*)d_in[8];
        Wv  = (const float*)d_in[9];    bv  = (const float*)d_in[10];
        Wiq = (const float*)d_in[11];   biq = (const float*)d_in[12];
        Wik = (const float*)d_in[13];   bik = (const float*)d_in[14];
        Wiv = (const float*)d_in[15];   biv = (const float*)d_in[16];
        Wo  = (const float*)d_in[17];   bo  = (const float*)d_in[18];
        W_O = (const float*)d_in[19];
        W_val = (const float*)d_in[20]; b_val = (const float*)d_in[21];
        W_adv = (const float*)d_in[22]; b_adv = (const float*)d_in[23];
    } else {
        hid   = (const float*)d_in[0];  act  = (const float*)d_in[1];
        W_enc = (const float*)d_in[2];  b_enc = (const float*)d_in[3];
        Wq  = (const float*)d_in[4];    bq  = (const float*)d_in[5];
        Wk  = (const float*)d_in[6];    bk  = (const float*)d_in[7];
        Wv  = (const float*)d_in[8];    bv  = (const float*)d_in[9];
        Wiq = (const float*)d_in[10];   biq = (const float*)d_in[11];
        Wik = (const float*)d_in[12];   bik = (const float*)d_in[13];
        Wiv = (const float*)d_in[14];   biv = (const float*)d_in[15];
        Wo  = (const float*)d_in[16];   bo  = (const float*)d_in[17];
        W_O = (const float*)d_in[18];
        W_val = (const float*)d_in[19]; b_val = (const float*)d_in[20];
        W_adv = (const float*)d_in[21]; b_adv = (const float*)d_in[22];
        state = (const int*)  d_in[23];
    }

    fused_kernel<<<NB, 256>>>(hid, act, state, W_enc, b_enc,
                              Wq, bq, Wk, bk, Wv, bv,
                              Wiq, biq, Wik, bik, Wiv, biv,
                              Wo, bo, W_O, W_val, b_val, W_adv, b_adv,
                              (float*)d_out);
}